// round 13
// baseline (speedup 1.0000x reference)
#include <cuda_runtime.h>
#include <cuda_fp16.h>
#include <math.h>
#include <stdint.h>

#define NTOK  4096
#define DIM   1024
#define HID   2732
#define HPAD  2752          // 43 * 64
#define NEXP  8
#define NSLOT 8192
#define BK    32            // K halves per k-block
#define LDSH  40            // smem row stride in halves (80B): conflict-free ldsm
#define NST   4
#define NXB1  43            // HPAD/64   (GEMM1 BN=64 per matrix)
#define NXB2  8             // DIM/128   (GEMM2 BN=128)
#define NCTA  296           // 2 * 148 SMs
#define MAXRB 72            // max total rowblocks across experts
#define NCH2  512           // W2-convert chunks (GEMM1 tail work)
#define CCH   11008         // uint2 items per chunk = NEXP*DIM*(HPAD/4)/NCH2

#define ASTR  (128 * LDSH * 2)          // 10240 B per A stage
#define BSTR  (64 * LDSH * 2)           // 5120 B per B stage (64-row tile)
#define B2STR (128 * LDSH * 2)          // 10240 B per B stage (128-row tile)
#define B1OFF (NST * ASTR)
#define B3OFF (B1OFF + NST * BSTR)
#define SM1SZ (B3OFF + NST * BSTR)      // 81920
#define B2OFF (NST * ASTR)
#define SM2SZ (B2OFF + NST * B2STR)     // 81920

// ---------------- scratch (static device globals; no allocs allowed) --------
__device__ __half g_h  [(size_t)NSLOT * HPAD];          // 45 MB
__device__ __half g_xh [(size_t)NTOK * DIM];
__device__ __half g_w1h[(size_t)NEXP * HID * DIM];
__device__ __half g_w3h[(size_t)NEXP * HID * DIM];
__device__ __half g_w2h[(size_t)NEXP * DIM * HPAD];     // padded rows
__device__ int    g_expert[NSLOT];
__device__ float  g_wslot[NSLOT];
__device__ float  g_w[NSLOT];
__device__ int    g_tok[NSLOT];
// ctrl block (memset to 0 each launch): [0..7]=counts, [8..15]=cursors,
// [16]=tick1, [17]=tick2
__device__ int    g_ctrl[32];

// ---------------- PTX helpers ------------------------------------------------
__device__ __forceinline__ unsigned smem_u32(const void* p) {
    return (unsigned)__cvta_generic_to_shared(p);
}
__device__ __forceinline__ void cp16(unsigned dst, const void* src) {
    asm volatile("cp.async.cg.shared.global [%0], [%1], 16;" :: "r"(dst), "l"(src));
}
__device__ __forceinline__ void cp16z(unsigned dst, const void* src, int sz) {
    asm volatile("cp.async.cg.shared.global [%0], [%1], 16, %2;"
                 :: "r"(dst), "l"(src), "r"(sz));
}
__device__ __forceinline__ void cp_commit() { asm volatile("cp.async.commit_group;"); }
__device__ __forceinline__ void cp_wait2()  { asm volatile("cp.async.wait_group 2;"); }

__device__ __forceinline__ void ldsm_x4(unsigned addr, unsigned& r0, unsigned& r1,
                                        unsigned& r2, unsigned& r3) {
    asm volatile("ldmatrix.sync.aligned.m8n8.x4.shared.b16 {%0,%1,%2,%3}, [%4];"
                 : "=r"(r0), "=r"(r1), "=r"(r2), "=r"(r3) : "r"(addr));
}
__device__ __forceinline__ void mma_f16(float* c, const unsigned* a, unsigned b0, unsigned b1) {
    asm volatile(
        "mma.sync.aligned.m16n8k16.row.col.f32.f16.f16.f32 "
        "{%0,%1,%2,%3}, {%4,%5,%6,%7}, {%8,%9}, {%0,%1,%2,%3};"
        : "+f"(c[0]), "+f"(c[1]), "+f"(c[2]), "+f"(c[3])
        : "r"(a[0]), "r"(a[1]), "r"(a[2]), "r"(a[3]), "r"(b0), "r"(b1));
}
__device__ __forceinline__ uint2 f4_to_h4(float4 v) {
    __half2 a = __floats2half2_rn(v.x, v.y);
    __half2 b = __floats2half2_rn(v.z, v.w);
    uint2 o;
    o.x = *reinterpret_cast<unsigned*>(&a);
    o.y = *reinterpret_cast<unsigned*>(&b);
    return o;
}

// ---------------- weight converts: W1, W3 only (W2 in GEMM1 tail) ------------
__global__ void k_wconv(const float4* __restrict__ W1, const float4* __restrict__ W3) {
    int i0 = blockIdx.x * 256 + threadIdx.x;
    int S  = gridDim.x * 256;
    const int NW4 = NEXP * HID * DIM / 4;
    uint2* w1d = (uint2*)g_w1h;
    uint2* w3d = (uint2*)g_w3h;
    for (int i = i0; i < NW4; i += S) w1d[i] = f4_to_h4(W1[i]);
    for (int i = i0; i < NW4; i += S) w3d[i] = f4_to_h4(W3[i]);
}

// ---------------- scatter: local prefix from counts, atomic rank -------------
__global__ void k_scatter() {
    int s = blockIdx.x * 256 + threadIdx.x;
    if (s < NSLOT) {
        int ex = g_expert[s];
        int off = 0;
#pragma unroll
        for (int e = 0; e < NEXP; e++)
            if (e < ex) off += g_ctrl[e];
        int pos = off + atomicAdd(&g_ctrl[8 + ex], 1);
        g_tok[pos] = s >> 1;
        g_w[pos]   = g_wslot[s];
    }
}

// ---------------- routing (f32) + fused x -> fp16 convert --------------------
__global__ void k_route(const float* __restrict__ x, const float* __restrict__ wg) {
    __shared__ float4 s_wg[NEXP * DIM / 4];
    int tid = threadIdx.x;
    const float4* wg4 = (const float4*)wg;
    for (int i = tid; i < NEXP * DIM / 4; i += 256) s_wg[i] = wg4[i];
    __syncthreads();

    int warp = tid >> 5, lane = tid & 31;
    int tok = blockIdx.x * 8 + warp;
    if (tok >= NTOK) return;

    const float4* xr = (const float4*)(x + (size_t)tok * DIM);
    __half* xhrow = g_xh + (size_t)tok * DIM;
    float acc[NEXP];
#pragma unroll
    for (int e = 0; e < NEXP; e++) acc[e] = 0.f;
    for (int j = lane; j < DIM / 4; j += 32) {
        float4 xv = xr[j];
        *(uint2*)(xhrow + 4 * j) = f4_to_h4(xv);
#pragma unroll
        for (int e = 0; e < NEXP; e++) {
            float4 w = s_wg[e * (DIM / 4) + j];
            acc[e] += xv.x * w.x + xv.y * w.y + xv.z * w.z + xv.w * w.w;
        }
    }
#pragma unroll
    for (int e = 0; e < NEXP; e++)
        for (int o = 16; o; o >>= 1) acc[e] += __shfl_xor_sync(0xffffffffu, acc[e], o);

    if (lane == 0) {
        int e0 = 0;
#pragma unroll
        for (int e = 1; e < NEXP; e++) if (acc[e] > acc[e0]) e0 = e;
        int e1 = (e0 == 0) ? 1 : 0;
#pragma unroll
        for (int e = 0; e < NEXP; e++) if (e != e0 && acc[e] > acc[e1]) e1 = e;
        float p1  = expf(acc[e1] - acc[e0]);
        float inv = 1.f / (1.f + p1);
        g_expert[2 * tok]     = e0;  g_wslot[2 * tok]     = inv;
        g_expert[2 * tok + 1] = e1;  g_wslot[2 * tok + 1] = p1 * inv;
        atomicAdd(&g_ctrl[e0], 1);
        atomicAdd(&g_ctrl[e1], 1);
    }
}

// ---------------- per-CTA tile-table build -----------------------------------
#define BUILD_TABLE(NXB)                                                        \
    __shared__ int s_pe[MAXRB], s_prb[MAXRB], s_off[NEXP], s_ne[NEXP], s_nt;    \
    if (threadIdx.x == 0) {                                                     \
        int s = 0, np = 0;                                                      \
        for (int e = 0; e < NEXP; e++) {                                        \
            int c = g_ctrl[e];                                                  \
            s_off[e] = s; s_ne[e] = c;                                          \
            for (int rb = 0; rb * 128 < c; rb++) {                              \
                s_pe[np] = e; s_prb[np] = rb; np++;                             \
            }                                                                   \
            s += c;                                                             \
        }                                                                       \
        s_nt = np * (NXB);                                                      \
    }                                                                           \
    __syncthreads();

// ---------------- GEMM1: h = silu(X@W1^T)*(X@W3^T); tail does W2 convert ----
__global__ void __launch_bounds__(256, 2)
k_gemm1(const __half* __restrict__ xh, const __half* __restrict__ w1h,
        const __half* __restrict__ w3h, const float* __restrict__ W2) {
    extern __shared__ __half sm[];
    uint32_t sb0 = smem_u32(sm);
    __shared__ int s_tile;
    BUILD_TABLE(NXB1)

    int tid = threadIdx.x;
    int w = tid >> 5, lane = tid & 31;
    int wm = w >> 1, wn = w & 1;
    int a_r = lane & 15, a_c = (lane >> 4) * 8;
    int b_r = ((lane >> 4) << 3) + (lane & 7);
    int b_c = ((lane >> 3) & 1) * 8;

    int arow[2], aseg[2];
    uint32_t aW[2];
#pragma unroll
    for (int i = 0; i < 2; i++) {
        int c = tid + 256 * i;
        arow[i] = c >> 2; aseg[i] = c & 3;
        aW[i] = sb0 + 2 * (arow[i] * LDSH + aseg[i] * 8);
    }
    int brow = tid >> 2, bseg = tid & 3;
    uint32_t b1W = sb0 + B1OFF + 2 * (brow * LDSH + bseg * 8);
    uint32_t b3W = sb0 + B3OFF + 2 * (brow * LDSH + bseg * 8);

    for (;;) {
        __syncthreads();
        if (tid == 0) s_tile = atomicAdd(&g_ctrl[16], 1);
        __syncthreads();
        int t = s_tile;
        if (t >= s_nt) {
            // ---- tail: W2 f32 -> fp16 padded convert (idle CTAs only) ----
            int c = t - s_nt;
            if (c >= NCH2) break;
            const int R4 = HPAD / 4;
            const int NITEMS = NEXP * DIM * R4;
            int beg = c * CCH;
            int end = min(beg + CCH, NITEMS);
            for (int i = beg + tid; i < end; i += 256) {
                int row = i / R4;
                int c4  = (i - row * R4) * 4;
                uint2 o = make_uint2(0u, 0u);
                if (c4 < HID) o = f4_to_h4(*(const float4*)(W2 + (size_t)row * HID + c4));
                *(uint2*)(g_w2h + (size_t)row * HPAD + c4) = o;
            }
            continue;
        }
        int pi = t / NXB1, xb = t - pi * NXB1;
        int e = s_pe[pi], row0 = s_prb[pi] * 128;
        int ne = s_ne[e], base = s_off[e], col0 = xb * 64;

        const __half* aP[2];
#pragma unroll
        for (int i = 0; i < 2; i++)
            aP[i] = xh + (size_t)g_tok[base + min(row0 + arow[i], ne - 1)] * DIM + aseg[i] * 8;
        int n = col0 + brow;
        int nv = (n < HID) ? 16 : 0;
        int nc = min(n, HID - 1);
        const __half* b1p = w1h + ((size_t)e * HID + nc) * DIM + bseg * 8;
        const __half* b3p = w3h + ((size_t)e * HID + nc) * DIM + bseg * 8;

        float acc1[2][4][4], acc3[2][4][4];
#pragma unroll
        for (int ms = 0; ms < 2; ms++)
#pragma unroll
            for (int ns = 0; ns < 4; ns++)
#pragma unroll
                for (int i = 0; i < 4; i++) { acc1[ms][ns][i] = 0.f; acc3[ms][ns][i] = 0.f; }

#pragma unroll
        for (int s = 0; s < NST - 1; s++) {
#pragma unroll
            for (int i = 0; i < 2; i++) cp16(aW[i] + s * ASTR, aP[i] + s * BK);
            cp16z(b1W + s * BSTR, b1p + s * BK, nv);
            cp16z(b3W + s * BSTR, b3p + s * BK, nv);
            cp_commit();
        }

        const int NIT = DIM / BK;   // 32
        for (int it = 0; it < NIT; it++) {
            cp_wait2();
            __syncthreads();
            int pf = it + NST - 1;
            if (pf < NIT) {
                int s2 = pf % NST;
#pragma unroll
                for (int i = 0; i < 2; i++) cp16(aW[i] + s2 * ASTR, aP[i] + pf * BK);
                cp16z(b1W + s2 * BSTR, b1p + pf * BK, nv);
                cp16z(b3W + s2 * BSTR, b3p + pf * BK, nv);
            }
            cp_commit();
            int st = it % NST;
            uint32_t aBase  = sb0 + st * ASTR;
            uint32_t bBase1 = sb0 + B1OFF + st * BSTR;
            uint32_t bBase3 = sb0 + B3OFF + st * BSTR;
#pragma unroll
            for (int ks = 0; ks < 2; ks++) {
                unsigned a[2][4];
#pragma unroll
                for (int ms = 0; ms < 2; ms++) {
                    int m = wm * 32 + ms * 16;
                    ldsm_x4(aBase + 2 * ((m + a_r) * LDSH + ks * 16 + a_c),
                            a[ms][0], a[ms][1], a[ms][2], a[ms][3]);
                }
                unsigned b1r[4][2], b3r[4][2];
#pragma unroll
                for (int ns2 = 0; ns2 < 2; ns2++) {
                    int nn = wn * 32 + ns2 * 16;
                    unsigned r0, r1, r2, r3;
                    ldsm_x4(bBase1 + 2 * ((nn + b_r) * LDSH + ks * 16 + b_c), r0, r1, r2, r3);
                    b1r[ns2*2][0] = r0; b1r[ns2*2][1] = r1;
                    b1r[ns2*2+1][0] = r2; b1r[ns2*2+1][1] = r3;
                    ldsm_x4(bBase3 + 2 * ((nn + b_r) * LDSH + ks * 16 + b_c), r0, r1, r2, r3);
                    b3r[ns2*2][0] = r0; b3r[ns2*2][1] = r1;
                    b3r[ns2*2+1][0] = r2; b3r[ns2*2+1][1] = r3;
                }
#pragma unroll
                for (int ms = 0; ms < 2; ms++)
#pragma unroll
                    for (int ns = 0; ns < 4; ns++) {
                        mma_f16(acc1[ms][ns], a[ms], b1r[ns][0], b1r[ns][1]);
                        mma_f16(acc3[ms][ns], a[ms], b3r[ns][0], b3r[ns][1]);
                    }
            }
        }

        // epilogue: SwiGLU -> fp16 h
        int crow = lane >> 2, ccol = (lane & 3) * 2;
#pragma unroll
        for (int ms = 0; ms < 2; ms++) {
#pragma unroll
            for (int half_ = 0; half_ < 2; half_++) {
                int r = row0 + wm * 32 + ms * 16 + crow + half_ * 8;
                if (r < ne) {
                    __half* dst = g_h + (size_t)(base + r) * HPAD;
#pragma unroll
                    for (int ns = 0; ns < 4; ns++) {
                        int cc = col0 + wn * 32 + ns * 8 + ccol;
                        float z0 = acc1[ms][ns][half_ * 2 + 0];
                        float z1 = acc1[ms][ns][half_ * 2 + 1];
                        float t0 = acc3[ms][ns][half_ * 2 + 0];
                        float t1 = acc3[ms][ns][half_ * 2 + 1];
                        float v0 = z0 / (1.f + __expf(-z0)) * t0;
                        float v1 = z1 / (1.f + __expf(-z1)) * t1;
                        *(__half2*)(dst + cc) = __float22half2_rn(make_float2(v0, v1));
                    }
                }
            }
        }
    }
}

// ---------------- GEMM2: out += w*(h @ W2^T), BM=128 BN=128 -----------------
__global__ void __launch_bounds__(256, 2)
k_gemm2(const __half* __restrict__ w2h, float* __restrict__ out) {
    extern __shared__ __half sm[];
    uint32_t sb0 = smem_u32(sm);
    __shared__ int s_tile;
    BUILD_TABLE(NXB2)

    int tid = threadIdx.x;
    int w = tid >> 5, lane = tid & 31;
    int wm = w >> 1, wn = w & 1;
    int a_r = lane & 15, a_c = (lane >> 4) * 8;
    int b_r = ((lane >> 4) << 3) + (lane & 7);
    int b_c = ((lane >> 3) & 1) * 8;

    int arow[2], aseg[2];
    uint32_t aW[2];
#pragma unroll
    for (int i = 0; i < 2; i++) {
        int c = tid + 256 * i;
        arow[i] = c >> 2; aseg[i] = c & 3;
        aW[i] = sb0 + 2 * (arow[i] * LDSH + aseg[i] * 8);
    }
    int brow2[2], bseg2[2];
    uint32_t bW[2];
#pragma unroll
    for (int i = 0; i < 2; i++) {
        int c = tid + 256 * i;
        brow2[i] = c >> 2; bseg2[i] = c & 3;
        bW[i] = sb0 + B2OFF + 2 * (brow2[i] * LDSH + bseg2[i] * 8);
    }

    for (;;) {
        __syncthreads();
        if (tid == 0) s_tile = atomicAdd(&g_ctrl[17], 1);
        __syncthreads();
        int t = s_tile;
        if (t >= s_nt) break;
        int pi = t / NXB2, xb = t - pi * NXB2;
        int e = s_pe[pi], row0 = s_prb[pi] * 128;
        int ne = s_ne[e], base = s_off[e], col0 = xb * 128;

        const __half* aP[2];
#pragma unroll
        for (int i = 0; i < 2; i++)
            aP[i] = g_h + (size_t)(base + min(row0 + arow[i], ne - 1)) * HPAD + aseg[i] * 8;
        const __half* bP[2];
#pragma unroll
        for (int i = 0; i < 2; i++)
            bP[i] = w2h + ((size_t)e * DIM + col0 + brow2[i]) * HPAD + bseg2[i] * 8;

        float acc[2][8][4];
#pragma unroll
        for (int ms = 0; ms < 2; ms++)
#pragma unroll
            for (int ns = 0; ns < 8; ns++)
#pragma unroll
                for (int i = 0; i < 4; i++) acc[ms][ns][i] = 0.f;

#pragma unroll
        for (int s = 0; s < NST - 1; s++) {
#pragma unroll
            for (int i = 0; i < 2; i++) {
                cp16(aW[i] + s * ASTR,  aP[i] + s * BK);
                cp16(bW[i] + s * B2STR, bP[i] + s * BK);
            }
            cp_commit();
        }

        const int NIT = HPAD / BK;   // 86
        for (int it = 0; it < NIT; it++) {
            cp_wait2();
            __syncthreads();
            int pf = it + NST - 1;
            if (pf < NIT) {
                int s2 = pf % NST;
#pragma unroll
                for (int i = 0; i < 2; i++) {
                    cp16(aW[i] + s2 * ASTR,  aP[i] + pf * BK);
                    cp16(bW[i] + s2 * B2STR, bP[i] + pf * BK);
                }
            }
            cp_commit();
            int st = it % NST;
            uint32_t aBase = sb0 + st * ASTR;
            uint32_t bBase = sb0 + B2OFF + st * B2STR;
#pragma unroll
            for (int ks = 0; ks < 2; ks++) {
                unsigned a[2][4];
#pragma unroll
                for (int ms = 0; ms < 2; ms++) {
                    int m = wm * 32 + ms * 16;
                    ldsm_x4(aBase + 2 * ((m + a_r) * LDSH + ks * 16 + a_c),
                            a[ms][0], a[ms][1], a[ms][2], a[ms][3]);
                }
                unsigned br[8][2];
#pragma unroll
                for (int ns2 = 0; ns2 < 4; ns2++) {
                    int nn = wn * 64 + ns2 * 16;
                    unsigned r0, r1, r2, r3;
                    ldsm_x4(bBase + 2 * ((nn + b_r) * LDSH + ks * 16 + b_c), r0, r1, r2, r3);
                    br[ns2*2][0] = r0; br[ns2*2][1] = r1;
                    br[ns2*2+1][0] = r2; br[ns2*2+1][1] = r3;
                }
#pragma unroll
                for (int ms = 0; ms < 2; ms++)
#pragma unroll
                    for (int ns = 0; ns < 8; ns++)
                        mma_f16(acc[ms][ns], a[ms], br[ns][0], br[ns][1]);
            }
        }

        // epilogue: scale by combine weight, atomically accumulate into out
        int crow = lane >> 2, ccol = (lane & 3) * 2;
#pragma unroll
        for (int ms = 0; ms < 2; ms++) {
#pragma unroll
            for (int half_ = 0; half_ < 2; half_++) {
                int r = row0 + wm * 32 + ms * 16 + crow + half_ * 8;
                if (r < ne) {
                    int pos = base + r;
                    float wgt = g_w[pos];
                    float* dst = out + (size_t)g_tok[pos] * DIM;
#pragma unroll
                    for (int ns = 0; ns < 8; ns++) {
                        int cc = col0 + wn * 64 + ns * 8 + ccol;
                        atomicAdd(dst + cc,     wgt * acc[ms][ns][half_ * 2 + 0]);
                        atomicAdd(dst + cc + 1, wgt * acc[ms][ns][half_ * 2 + 1]);
                    }
                }
            }
        }
    }
}

// ---------------- launch -----------------------------------------------------
extern "C" void kernel_launch(void* const* d_in, const int* in_sizes, int n_in,
                              void* d_out, int out_size) {
    const float* x  = (const float*)d_in[0];
    const float* Wg = (const float*)d_in[1];
    const float* W1 = (const float*)d_in[2];
    const float* W2 = (const float*)d_in[3];
    const float* W3 = (const float*)d_in[4];
    float* out = (float*)d_out;
    (void)in_sizes; (void)n_in; (void)out_size;

    cudaFuncSetAttribute(k_gemm1, cudaFuncAttributeMaxDynamicSharedMemorySize, SM1SZ);
    cudaFuncSetAttribute(k_gemm2, cudaFuncAttributeMaxDynamicSharedMemorySize, SM2SZ);

    __half *xh, *w1h, *w3h, *w2h;
    int* ctrl;
    cudaGetSymbolAddress((void**)&xh,   g_xh);
    cudaGetSymbolAddress((void**)&w1h,  g_w1h);
    cudaGetSymbolAddress((void**)&w3h,  g_w3h);
    cudaGetSymbolAddress((void**)&w2h,  g_w2h);
    cudaGetSymbolAddress((void**)&ctrl, g_ctrl);

    cudaMemsetAsync(ctrl, 0, 32 * sizeof(int));
    cudaMemsetAsync(out, 0, (size_t)NTOK * DIM * sizeof(float));
    k_route   <<<NTOK / 8, 256>>>(x, Wg);
    k_wconv   <<<2048, 256>>>((const float4*)W1, (const float4*)W3);
    k_scatter <<<NSLOT / 256, 256>>>();
    k_gemm1   <<<NCTA, 256, SM1SZ>>>(xh, w1h, w3h, W2);
    k_gemm2   <<<NCTA, 256, SM2SZ>>>(w2h, out);
}

// round 14
// speedup vs baseline: 1.1038x; 1.1038x over previous
#include <cuda_runtime.h>
#include <cuda_fp16.h>
#include <math.h>
#include <stdint.h>

#define NTOK  4096
#define DIM   1024
#define HID   2732
#define HPAD  2752          // 43 * 64
#define NEXP  8
#define NSLOT 8192
#define BK    64            // K halves per k-block (was 32)
#define LDSH  72            // smem row stride in halves (144B): conflict-free ldsm
#define NST   3
#define NXB1  43            // HPAD/64   (GEMM1 BN=64 per matrix)
#define NXB2  8             // DIM/128   (GEMM2 BN=128)
#define NCTA  296           // 2 * 148 SMs
#define MAXRB 72

#define ASTR  (128 * LDSH * 2)          // 18432 B per A stage
#define BSTR  (64 * LDSH * 2)           // 9216 B per B stage (64-row tile)
#define B2STR (128 * LDSH * 2)          // 18432 B per B stage (128-row tile)
#define B1OFF (NST * ASTR)              // 55296
#define B3OFF (B1OFF + NST * BSTR)      // 82944
#define SM1SZ (B3OFF + NST * BSTR)      // 110592
#define B2OFF (NST * ASTR)
#define SM2SZ (B2OFF + NST * B2STR)     // 110592

// ---------------- scratch (static device globals; no allocs allowed) --------
__device__ __half g_h  [(size_t)NSLOT * HPAD];          // 45 MB
__device__ __half g_xh [(size_t)NTOK * DIM];
__device__ __half g_w1h[(size_t)NEXP * HID * DIM];
__device__ __half g_w3h[(size_t)NEXP * HID * DIM];
__device__ __half g_w2h[(size_t)NEXP * DIM * HPAD];     // padded rows
__device__ int    g_expert[NSLOT];
__device__ float  g_wslot[NSLOT];
__device__ float  g_w[NSLOT];
__device__ int    g_tok[NSLOT];
// ctrl (memset 0): [0..7]=counts, [8..15]=cursors, [16]=tick1, [17]=tick2
__device__ int    g_ctrl[32];

// ---------------- PTX helpers ------------------------------------------------
__device__ __forceinline__ unsigned smem_u32(const void* p) {
    return (unsigned)__cvta_generic_to_shared(p);
}
__device__ __forceinline__ void cp16(unsigned dst, const void* src) {
    asm volatile("cp.async.cg.shared.global [%0], [%1], 16;" :: "r"(dst), "l"(src));
}
__device__ __forceinline__ void cp16z(unsigned dst, const void* src, int sz) {
    asm volatile("cp.async.cg.shared.global [%0], [%1], 16, %2;"
                 :: "r"(dst), "l"(src), "r"(sz));
}
__device__ __forceinline__ void cp_commit() { asm volatile("cp.async.commit_group;"); }
__device__ __forceinline__ void cp_wait1()  { asm volatile("cp.async.wait_group 1;"); }

__device__ __forceinline__ void ldsm_x4(unsigned addr, unsigned& r0, unsigned& r1,
                                        unsigned& r2, unsigned& r3) {
    asm volatile("ldmatrix.sync.aligned.m8n8.x4.shared.b16 {%0,%1,%2,%3}, [%4];"
                 : "=r"(r0), "=r"(r1), "=r"(r2), "=r"(r3) : "r"(addr));
}
__device__ __forceinline__ void mma_f16(float* c, const unsigned* a, unsigned b0, unsigned b1) {
    asm volatile(
        "mma.sync.aligned.m16n8k16.row.col.f32.f16.f16.f32 "
        "{%0,%1,%2,%3}, {%4,%5,%6,%7}, {%8,%9}, {%0,%1,%2,%3};"
        : "+f"(c[0]), "+f"(c[1]), "+f"(c[2]), "+f"(c[3])
        : "r"(a[0]), "r"(a[1]), "r"(a[2]), "r"(a[3]), "r"(b0), "r"(b1));
}
__device__ __forceinline__ uint2 f4_to_h4(float4 v) {
    __half2 a = __floats2half2_rn(v.x, v.y);
    __half2 b = __floats2half2_rn(v.z, v.w);
    uint2 o;
    o.x = *reinterpret_cast<unsigned*>(&a);
    o.y = *reinterpret_cast<unsigned*>(&b);
    return o;
}

// ---------------- weight converts --------------------------------------------
__global__ void k_wconv(const float4* __restrict__ W1, const float4* __restrict__ W3,
                        const float* __restrict__ W2) {
    int i0 = blockIdx.x * 256 + threadIdx.x;
    int S  = gridDim.x * 256;
    const int NW4 = NEXP * HID * DIM / 4;
    uint2* w1d = (uint2*)g_w1h;
    uint2* w3d = (uint2*)g_w3h;
    for (int i = i0; i < NW4; i += S) w1d[i] = f4_to_h4(W1[i]);
    for (int i = i0; i < NW4; i += S) w3d[i] = f4_to_h4(W3[i]);
    const int R4 = HPAD / 4;
    const int n2 = NEXP * DIM * R4;
    for (int i = i0; i < n2; i += S) {
        int row = i / R4;
        int c4  = (i - row * R4) * 4;
        uint2 o = make_uint2(0u, 0u);
        if (c4 < HID) o = f4_to_h4(*(const float4*)(W2 + (size_t)row * HID + c4));
        *(uint2*)(g_w2h + (size_t)row * HPAD + c4) = o;
    }
}

// ---------------- scatter ----------------------------------------------------
__global__ void k_scatter() {
    int s = blockIdx.x * 256 + threadIdx.x;
    if (s < NSLOT) {
        int ex = g_expert[s];
        int off = 0;
#pragma unroll
        for (int e = 0; e < NEXP; e++)
            if (e < ex) off += g_ctrl[e];
        int pos = off + atomicAdd(&g_ctrl[8 + ex], 1);
        g_tok[pos] = s >> 1;
        g_w[pos]   = g_wslot[s];
    }
}

// ---------------- routing (f32) + fused x -> fp16 convert --------------------
__global__ void k_route(const float* __restrict__ x, const float* __restrict__ wg) {
    __shared__ float4 s_wg[NEXP * DIM / 4];
    int tid = threadIdx.x;
    const float4* wg4 = (const float4*)wg;
    for (int i = tid; i < NEXP * DIM / 4; i += 256) s_wg[i] = wg4[i];
    __syncthreads();

    int warp = tid >> 5, lane = tid & 31;
    int tok = blockIdx.x * 8 + warp;
    if (tok >= NTOK) return;

    const float4* xr = (const float4*)(x + (size_t)tok * DIM);
    __half* xhrow = g_xh + (size_t)tok * DIM;
    float acc[NEXP];
#pragma unroll
    for (int e = 0; e < NEXP; e++) acc[e] = 0.f;
    for (int j = lane; j < DIM / 4; j += 32) {
        float4 xv = xr[j];
        *(uint2*)(xhrow + 4 * j) = f4_to_h4(xv);
#pragma unroll
        for (int e = 0; e < NEXP; e++) {
            float4 w = s_wg[e * (DIM / 4) + j];
            acc[e] += xv.x * w.x + xv.y * w.y + xv.z * w.z + xv.w * w.w;
        }
    }
#pragma unroll
    for (int e = 0; e < NEXP; e++)
        for (int o = 16; o; o >>= 1) acc[e] += __shfl_xor_sync(0xffffffffu, acc[e], o);

    if (lane == 0) {
        int e0 = 0;
#pragma unroll
        for (int e = 1; e < NEXP; e++) if (acc[e] > acc[e0]) e0 = e;
        int e1 = (e0 == 0) ? 1 : 0;
#pragma unroll
        for (int e = 0; e < NEXP; e++) if (e != e0 && acc[e] > acc[e1]) e1 = e;
        float p1  = expf(acc[e1] - acc[e0]);
        float inv = 1.f / (1.f + p1);
        g_expert[2 * tok]     = e0;  g_wslot[2 * tok]     = inv;
        g_expert[2 * tok + 1] = e1;  g_wslot[2 * tok + 1] = p1 * inv;
        atomicAdd(&g_ctrl[e0], 1);
        atomicAdd(&g_ctrl[e1], 1);
    }
}

// ---------------- per-CTA tile-table build -----------------------------------
#define BUILD_TABLE(NXB)                                                        \
    __shared__ int s_pe[MAXRB], s_prb[MAXRB], s_off[NEXP], s_ne[NEXP], s_nt;    \
    if (threadIdx.x == 0) {                                                     \
        int s = 0, np = 0;                                                      \
        for (int e = 0; e < NEXP; e++) {                                        \
            int c = g_ctrl[e];                                                  \
            s_off[e] = s; s_ne[e] = c;                                          \
            for (int rb = 0; rb * 128 < c; rb++) {                              \
                s_pe[np] = e; s_prb[np] = rb; np++;                             \
            }                                                                   \
            s += c;                                                             \
        }                                                                       \
        s_nt = np * (NXB);                                                      \
    }                                                                           \
    __syncthreads();

// ---------------- GEMM1: h = silu(X@W1^T)*(X@W3^T), BK=64 -------------------
__global__ void __launch_bounds__(256, 2)
k_gemm1(const __half* __restrict__ xh, const __half* __restrict__ w1h,
        const __half* __restrict__ w3h) {
    extern __shared__ __half sm[];
    uint32_t sb0 = smem_u32(sm);
    __shared__ int s_tile;
    BUILD_TABLE(NXB1)

    const char* xb_  = (const char*)xh;
    const char* w1b_ = (const char*)w1h;
    const char* w3b_ = (const char*)w3h;

    int tid = threadIdx.x;
    int w = tid >> 5, lane = tid & 31;
    int wm = w >> 1, wn = w & 1;
    int a_r = lane & 15, a_c = (lane >> 4) * 8;
    int b_r = ((lane >> 4) << 3) + (lane & 7);
    int b_c = ((lane >> 3) & 1) * 8;

    // A loaders: 4 x 16B per thread per stage (rows c>>3, seg c&7)
    int ar[4], as_[4];
    uint32_t aW[4];
#pragma unroll
    for (int i = 0; i < 4; i++) {
        int c = tid + 256 * i;
        ar[i] = c >> 3; as_[i] = c & 7;
        aW[i] = sb0 + 2 * (ar[i] * LDSH + as_[i] * 8);
    }
    // B loaders: 2 x 16B per thread per stage per matrix
    int br_[2], bs_[2];
    uint32_t b1W[2], b3W[2];
#pragma unroll
    for (int i = 0; i < 2; i++) {
        int c = tid + 256 * i;
        br_[i] = c >> 3; bs_[i] = c & 7;
        b1W[i] = sb0 + B1OFF + 2 * (br_[i] * LDSH + bs_[i] * 8);
        b3W[i] = sb0 + B3OFF + 2 * (br_[i] * LDSH + bs_[i] * 8);
    }

    for (;;) {
        __syncthreads();
        if (tid == 0) s_tile = atomicAdd(&g_ctrl[16], 1);
        __syncthreads();
        int t = s_tile;
        if (t >= s_nt) break;
        int pi = t / NXB1, xb = t - pi * NXB1;
        int e = s_pe[pi], row0 = s_prb[pi] * 128;
        int ne = s_ne[e], base = s_off[e], col0 = xb * 64;

        uint32_t aO[4];
#pragma unroll
        for (int i = 0; i < 4; i++)
            aO[i] = (uint32_t)((g_tok[base + min(row0 + ar[i], ne - 1)] * DIM + as_[i] * 8) * 2);
        uint32_t bO[2];
        int nv[2];
#pragma unroll
        for (int i = 0; i < 2; i++) {
            int n = col0 + br_[i];
            nv[i] = (n < HID) ? 16 : 0;
            bO[i] = (uint32_t)(((e * HID + min(n, HID - 1)) * DIM + bs_[i] * 8) * 2);
        }

        float acc1[2][4][4], acc3[2][4][4];
#pragma unroll
        for (int ms = 0; ms < 2; ms++)
#pragma unroll
            for (int ns = 0; ns < 4; ns++)
#pragma unroll
                for (int i = 0; i < 4; i++) { acc1[ms][ns][i] = 0.f; acc3[ms][ns][i] = 0.f; }

        // prologue: stages 0,1  (k-bytes advance = it * BK * 2 = it * 128)
#pragma unroll
        for (int s = 0; s < NST - 1; s++) {
#pragma unroll
            for (int i = 0; i < 4; i++) cp16(aW[i] + s * ASTR, xb_ + aO[i] + s * 128);
#pragma unroll
            for (int i = 0; i < 2; i++) {
                cp16z(b1W[i] + s * BSTR, w1b_ + bO[i] + s * 128, nv[i]);
                cp16z(b3W[i] + s * BSTR, w3b_ + bO[i] + s * 128, nv[i]);
            }
            cp_commit();
        }

        const int NIT = DIM / BK;   // 16
        for (int it = 0; it < NIT; it++) {
            cp_wait1();
            __syncthreads();
            int pf = it + NST - 1;
            if (pf < NIT) {
                int s2 = pf % NST;
#pragma unroll
                for (int i = 0; i < 4; i++) cp16(aW[i] + s2 * ASTR, xb_ + aO[i] + pf * 128);
#pragma unroll
                for (int i = 0; i < 2; i++) {
                    cp16z(b1W[i] + s2 * BSTR, w1b_ + bO[i] + pf * 128, nv[i]);
                    cp16z(b3W[i] + s2 * BSTR, w3b_ + bO[i] + pf * 128, nv[i]);
                }
            }
            cp_commit();
            int st = it % NST;
            uint32_t aBase  = sb0 + st * ASTR;
            uint32_t bBase1 = sb0 + B1OFF + st * BSTR;
            uint32_t bBase3 = sb0 + B3OFF + st * BSTR;
#pragma unroll
            for (int ks = 0; ks < 4; ks++) {
                unsigned a[2][4];
#pragma unroll
                for (int ms = 0; ms < 2; ms++) {
                    int m = wm * 32 + ms * 16;
                    ldsm_x4(aBase + 2 * ((m + a_r) * LDSH + ks * 16 + a_c),
                            a[ms][0], a[ms][1], a[ms][2], a[ms][3]);
                }
                unsigned b1r[4][2], b3r[4][2];
#pragma unroll
                for (int ns2 = 0; ns2 < 2; ns2++) {
                    int nn = wn * 32 + ns2 * 16;
                    unsigned r0, r1, r2, r3;
                    ldsm_x4(bBase1 + 2 * ((nn + b_r) * LDSH + ks * 16 + b_c), r0, r1, r2, r3);
                    b1r[ns2*2][0] = r0; b1r[ns2*2][1] = r1;
                    b1r[ns2*2+1][0] = r2; b1r[ns2*2+1][1] = r3;
                    ldsm_x4(bBase3 + 2 * ((nn + b_r) * LDSH + ks * 16 + b_c), r0, r1, r2, r3);
                    b3r[ns2*2][0] = r0; b3r[ns2*2][1] = r1;
                    b3r[ns2*2+1][0] = r2; b3r[ns2*2+1][1] = r3;
                }
#pragma unroll
                for (int ms = 0; ms < 2; ms++)
#pragma unroll
                    for (int ns = 0; ns < 4; ns++) {
                        mma_f16(acc1[ms][ns], a[ms], b1r[ns][0], b1r[ns][1]);
                        mma_f16(acc3[ms][ns], a[ms], b3r[ns][0], b3r[ns][1]);
                    }
            }
        }

        // epilogue: SwiGLU -> fp16 h
        int crow = lane >> 2, ccol = (lane & 3) * 2;
#pragma unroll
        for (int ms = 0; ms < 2; ms++) {
#pragma unroll
            for (int half_ = 0; half_ < 2; half_++) {
                int r = row0 + wm * 32 + ms * 16 + crow + half_ * 8;
                if (r < ne) {
                    __half* dst = g_h + (size_t)(base + r) * HPAD;
#pragma unroll
                    for (int ns = 0; ns < 4; ns++) {
                        int cc = col0 + wn * 32 + ns * 8 + ccol;
                        float z0 = acc1[ms][ns][half_ * 2 + 0];
                        float z1 = acc1[ms][ns][half_ * 2 + 1];
                        float t0 = acc3[ms][ns][half_ * 2 + 0];
                        float t1 = acc3[ms][ns][half_ * 2 + 1];
                        float v0 = z0 / (1.f + __expf(-z0)) * t0;
                        float v1 = z1 / (1.f + __expf(-z1)) * t1;
                        *(__half2*)(dst + cc) = __float22half2_rn(make_float2(v0, v1));
                    }
                }
            }
        }
    }
}

// ---------------- GEMM2: out += w*(h @ W2^T), BM=128 BN=128, BK=64 ----------
__global__ void __launch_bounds__(256, 2)
k_gemm2(const __half* __restrict__ w2h, float* __restrict__ out) {
    extern __shared__ __half sm[];
    uint32_t sb0 = smem_u32(sm);
    __shared__ int s_tile;
    BUILD_TABLE(NXB2)

    const char* hb_ = (const char*)g_h;
    const char* wb_ = (const char*)w2h;

    int tid = threadIdx.x;
    int w = tid >> 5, lane = tid & 31;
    int wm = w >> 1, wn = w & 1;
    int a_r = lane & 15, a_c = (lane >> 4) * 8;
    int b_r = ((lane >> 4) << 3) + (lane & 7);
    int b_c = ((lane >> 3) & 1) * 8;

    int ar[4], as_[4];
    uint32_t aW[4], bW[4];
#pragma unroll
    for (int i = 0; i < 4; i++) {
        int c = tid + 256 * i;
        ar[i] = c >> 3; as_[i] = c & 7;
        aW[i] = sb0 + 2 * (ar[i] * LDSH + as_[i] * 8);
        bW[i] = sb0 + B2OFF + 2 * (ar[i] * LDSH + as_[i] * 8);
    }

    for (;;) {
        __syncthreads();
        if (tid == 0) s_tile = atomicAdd(&g_ctrl[17], 1);
        __syncthreads();
        int t = s_tile;
        if (t >= s_nt) break;
        int pi = t / NXB2, xb = t - pi * NXB2;
        int e = s_pe[pi], row0 = s_prb[pi] * 128;
        int ne = s_ne[e], base = s_off[e], col0 = xb * 128;

        uint32_t aO[4], bO[4];
#pragma unroll
        for (int i = 0; i < 4; i++) {
            int r = min(row0 + ar[i], ne - 1);
            aO[i] = (uint32_t)(((base + r) * HPAD + as_[i] * 8) * 2);
            bO[i] = (uint32_t)(((e * DIM + col0 + ar[i]) * HPAD + as_[i] * 8) * 2);
        }

        float acc[2][8][4];
#pragma unroll
        for (int ms = 0; ms < 2; ms++)
#pragma unroll
            for (int ns = 0; ns < 8; ns++)
#pragma unroll
                for (int i = 0; i < 4; i++) acc[ms][ns][i] = 0.f;

#pragma unroll
        for (int s = 0; s < NST - 1; s++) {
#pragma unroll
            for (int i = 0; i < 4; i++) {
                cp16(aW[i] + s * ASTR,  hb_ + aO[i] + s * 128);
                cp16(bW[i] + s * B2STR, wb_ + bO[i] + s * 128);
            }
            cp_commit();
        }

        const int NIT = HPAD / BK;   // 43
        for (int it = 0; it < NIT; it++) {
            cp_wait1();
            __syncthreads();
            int pf = it + NST - 1;
            if (pf < NIT) {
                int s2 = pf % NST;
#pragma unroll
                for (int i = 0; i < 4; i++) {
                    cp16(aW[i] + s2 * ASTR,  hb_ + aO[i] + pf * 128);
                    cp16(bW[i] + s2 * B2STR, wb_ + bO[i] + pf * 128);
                }
            }
            cp_commit();
            int st = it % NST;
            uint32_t aBase = sb0 + st * ASTR;
            uint32_t bBase = sb0 + B2OFF + st * B2STR;
#pragma unroll
            for (int ks = 0; ks < 4; ks++) {
                unsigned a[2][4];
#pragma unroll
                for (int ms = 0; ms < 2; ms++) {
                    int m = wm * 32 + ms * 16;
                    ldsm_x4(aBase + 2 * ((m + a_r) * LDSH + ks * 16 + a_c),
                            a[ms][0], a[ms][1], a[ms][2], a[ms][3]);
                }
                unsigned br[8][2];
#pragma unroll
                for (int ns2 = 0; ns2 < 4; ns2++) {
                    int nn = wn * 64 + ns2 * 16;
                    unsigned r0, r1, r2, r3;
                    ldsm_x4(bBase + 2 * ((nn + b_r) * LDSH + ks * 16 + b_c), r0, r1, r2, r3);
                    br[ns2*2][0] = r0; br[ns2*2][1] = r1;
                    br[ns2*2+1][0] = r2; br[ns2*2+1][1] = r3;
                }
#pragma unroll
                for (int ms = 0; ms < 2; ms++)
#pragma unroll
                    for (int ns = 0; ns < 8; ns++)
                        mma_f16(acc[ms][ns], a[ms], br[ns][0], br[ns][1]);
            }
        }

        // epilogue: scale by combine weight, atomically accumulate into out
        int crow = lane >> 2, ccol = (lane & 3) * 2;
#pragma unroll
        for (int ms = 0; ms < 2; ms++) {
#pragma unroll
            for (int half_ = 0; half_ < 2; half_++) {
                int r = row0 + wm * 32 + ms * 16 + crow + half_ * 8;
                if (r < ne) {
                    int pos = base + r;
                    float wgt = g_w[pos];
                    float* dst = out + (size_t)g_tok[pos] * DIM;
#pragma unroll
                    for (int ns = 0; ns < 8; ns++) {
                        int cc = col0 + wn * 64 + ns * 8 + ccol;
                        atomicAdd(dst + cc,     wgt * acc[ms][ns][half_ * 2 + 0]);
                        atomicAdd(dst + cc + 1, wgt * acc[ms][ns][half_ * 2 + 1]);
                    }
                }
            }
        }
    }
}

// ---------------- launch -----------------------------------------------------
extern "C" void kernel_launch(void* const* d_in, const int* in_sizes, int n_in,
                              void* d_out, int out_size) {
    const float* x  = (const float*)d_in[0];
    const float* Wg = (const float*)d_in[1];
    const float* W1 = (const float*)d_in[2];
    const float* W2 = (const float*)d_in[3];
    const float* W3 = (const float*)d_in[4];
    float* out = (float*)d_out;
    (void)in_sizes; (void)n_in; (void)out_size;

    cudaFuncSetAttribute(k_gemm1, cudaFuncAttributeMaxDynamicSharedMemorySize, SM1SZ);
    cudaFuncSetAttribute(k_gemm2, cudaFuncAttributeMaxDynamicSharedMemorySize, SM2SZ);

    __half *xh, *w1h, *w3h, *w2h;
    int* ctrl;
    cudaGetSymbolAddress((void**)&xh,   g_xh);
    cudaGetSymbolAddress((void**)&w1h,  g_w1h);
    cudaGetSymbolAddress((void**)&w3h,  g_w3h);
    cudaGetSymbolAddress((void**)&w2h,  g_w2h);
    cudaGetSymbolAddress((void**)&ctrl, g_ctrl);

    cudaMemsetAsync(ctrl, 0, 32 * sizeof(int));
    cudaMemsetAsync(out, 0, (size_t)NTOK * DIM * sizeof(float));
    k_route   <<<NTOK / 8, 256>>>(x, Wg);
    k_wconv   <<<2048, 256>>>((const float4*)W1, (const float4*)W3, W2);
    k_scatter <<<NSLOT / 256, 256>>>();
    k_gemm1   <<<NCTA, 256, SM1SZ>>>(xh, w1h, w3h);
    k_gemm2   <<<NCTA, 256, SM2SZ>>>(w2h, out);
}